// round 11
// baseline (speedup 1.0000x reference)
#include <cuda_runtime.h>
#include <cuda_bf16.h>
#include <cstdint>

// SoftPool_2d: x (32,128,128,64) f32, 2x2/stride-2 windows.
// Round 10: operand-role swap. GEMM is C[j,pos] = We^T(128x64, A, row-major)
// @ win^T (B). We fragments are REGISTER-RESIDENT (loaded once): warp pair
// splits hidden 64/64. Per pass (16 positions) the only smem GEMM traffic is
// the 2KB win tile per warp (256B/pos vs 768B/pos in round 9). Logit dot
// combined across the pair via smem partials + named barriers.

#define THREADS 256

// dynamic smem (bytes)
#define OFF_WT   0          // We^T bf16 SW128: 128 rows x 128B   (16384)
#define OFF_WIN  16384      // per-pair win tile: 4 x 2048        (8192)
#define OFF_BIAS 24576      // 128 f32
#define OFF_WR   25088      // 128 f32
#define OFF_PART 25600      // 4 pairs x 2 halves x 16 pos f32    (512)
#define SMEM_SZ  26112

__device__ __forceinline__ float tanh_fast(float x) {
    float y; asm("tanh.approx.f32 %0, %1;" : "=f"(y) : "f"(x)); return y;
}
__device__ __forceinline__ uint32_t pkbf2(float lo, float hi) {
    __nv_bfloat162 h = __floats2bfloat162_rn(lo, hi);
    return *reinterpret_cast<uint32_t*>(&h);
}
__device__ __forceinline__ void mma16816(float* c, const uint32_t* a,
                                         uint32_t b0, uint32_t b1) {
    asm volatile(
        "mma.sync.aligned.m16n8k16.row.col.f32.bf16.bf16.f32 "
        "{%0,%1,%2,%3}, {%4,%5,%6,%7}, {%8,%9}, {%0,%1,%2,%3};"
        : "+f"(c[0]), "+f"(c[1]), "+f"(c[2]), "+f"(c[3])
        : "r"(a[0]), "r"(a[1]), "r"(a[2]), "r"(a[3]), "r"(b0), "r"(b1));
}
__device__ __forceinline__ void ldsm_x4(uint32_t* r, uint32_t addr) {
    asm volatile("ldmatrix.sync.aligned.m8n8.x4.shared.b16 {%0,%1,%2,%3}, [%4];"
                 : "=r"(r[0]), "=r"(r[1]), "=r"(r[2]), "=r"(r[3]) : "r"(addr));
}
__device__ __forceinline__ uint32_t swz(uint32_t off) {
    return off ^ ((off >> 3) & 0x70);
}
__device__ __forceinline__ void pair_bar(int id) {
    asm volatile("bar.sync %0, %1;" :: "r"(id), "r"(64) : "memory");
}

__global__ __launch_bounds__(THREADS, 2)
void softpool2d_mma_kernel(const float* __restrict__ x,
                           const float* __restrict__ We,
                           const float* __restrict__ be,
                           const float* __restrict__ Wr,
                           const float* __restrict__ br,
                           float* __restrict__ out)
{
    extern __shared__ __align__(16) unsigned char smemb[];
    float* sBias = reinterpret_cast<float*>(smemb + OFF_BIAS);
    float* sWr   = reinterpret_cast<float*>(smemb + OFF_WR);
    float* sPart = reinterpret_cast<float*>(smemb + OFF_PART);

    const int tid  = threadIdx.x;
    const int wid  = tid >> 5;
    const int lane = tid & 31;
    const int pr   = wid >> 1;        // pair 0..3
    const int h    = wid & 1;         // hidden half
    const int g    = lane >> 2;
    const int tq   = lane & 3;
    const int pl   = h * 32 + lane;   // pair-local thread 0..63

    // Stage We^T (SW128): row j holds We[:,j] as bf16
    {
        uint8_t* bp = smemb + OFF_WT;
        for (int idx = tid; idx < 64 * 128; idx += THREADS) {
            int d = idx >> 7;
            int j = idx & 127;
            *reinterpret_cast<__nv_bfloat16*>(bp + swz((uint32_t)(j * 128 + d * 2)))
                = __float2bfloat16(We[idx]);
        }
    }
    if (tid < 128) {
        sBias[tid] = be[tid];
        sWr[tid]   = Wr[tid];
    }
    __syncthreads();

    const float brv = br[0];
    const uint32_t wtW  = (uint32_t)__cvta_generic_to_shared(smemb + OFF_WT);
    const uint32_t winW = (uint32_t)__cvta_generic_to_shared(smemb + OFF_WIN)
                          + pr * 2048;

    // Resident A fragments: warp's 64 hidden rows, 4 m-tiles x 4 k-steps.
    uint32_t af[64];
    {
        const uint32_t arow = (uint32_t)((lane & 15) * 128 + (lane >> 4) * 16);
#pragma unroll
        for (int mt = 0; mt < 4; ++mt)
#pragma unroll
            for (int kk = 0; kk < 4; ++kk)
                ldsm_x4(&af[(mt * 4 + kk) * 4],
                        wtW + swz((uint32_t)((h * 64 + mt * 16) * 128)
                                  + arow + kk * 32));
    }

    const int cta = blockIdx.x;
    const int b   = cta >> 6;
    const int q   = cta & 63;
    const int row0 = b * 128 + 2 * q;

    const int quad = lane >> 3;
    const uint32_t brow = (uint32_t)(((quad >> 1) * 8 + (lane & 7)) * 128
                                     + (quad & 1) * 16);
    float* sPp = sPart + pr * 32;

    for (int t = 0; t < 4; ++t) {
        const int pw = pr * 16 + t * 4;     // pass covers windows pw..pw+3
        const float* __restrict__ bt = x + ((size_t)row0 * 128 + 2 * pw) * 64;

        // Stage win tile (16 pos x 64 ch bf16, SW128): 64 threads x 4 chunks.
        // Row m = i*4 + w (i = pos in 2x2 row-major, w = window 0..3).
#pragma unroll
        for (int it = 0; it < 4; ++it) {
            int ci = it * 64 + pl;          // 0..255
            int m  = ci >> 4;
            int c4 = ci & 15;
            int i  = m >> 2, w = m & 3;
            const float4 v = *reinterpret_cast<const float4*>(
                bt + (i >> 1) * 8192 + w * 128 + (i & 1) * 64 + c4 * 4);
            uint32_t lo = pkbf2(v.x, v.y);
            uint32_t hi = pkbf2(v.z, v.w);
            asm volatile("st.shared.v2.b32 [%0], {%1,%2};"
                         :: "r"(winW + swz((uint32_t)(m * 128 + c4 * 8))),
                            "r"(lo), "r"(hi) : "memory");
        }
        pair_bar(1 + pr);

        // GEMM: acc[mt][nt][c] = C[j, pos]
        float acc[4][2][4];
#pragma unroll
        for (int mt = 0; mt < 4; ++mt)
#pragma unroll
            for (int nt = 0; nt < 2; ++nt)
#pragma unroll
                for (int c = 0; c < 4; ++c) acc[mt][nt][c] = 0.0f;

#pragma unroll
        for (int kk = 0; kk < 4; ++kk) {
            uint32_t brr[4];
            ldsm_x4(brr, winW + swz(brow + kk * 32));
#pragma unroll
            for (int mt = 0; mt < 4; ++mt) {
                mma16816(acc[mt][0], &af[(mt * 4 + kk) * 4], brr[0], brr[1]);
                mma16816(acc[mt][1], &af[(mt * 4 + kk) * 4], brr[2], brr[3]);
            }
        }

        // Partial logit dot over this warp's 64 hidden rows.
        // Lane holds rows j0=h*64+mt*16+g, j1=j0+8; cols tq*2+{0,1} per nt.
        float s[4] = {0.0f, 0.0f, 0.0f, 0.0f};
#pragma unroll
        for (int mt = 0; mt < 4; ++mt) {
            const int j0 = h * 64 + mt * 16 + g;
            const float b0 = sBias[j0],     w0 = sWr[j0];
            const float b1 = sBias[j0 + 8], w1 = sWr[j0 + 8];
#pragma unroll
            for (int nt = 0; nt < 2; ++nt) {
                s[nt * 2 + 0] += tanh_fast(acc[mt][nt][0] + b0) * w0
                               + tanh_fast(acc[mt][nt][2] + b1) * w1;
                s[nt * 2 + 1] += tanh_fast(acc[mt][nt][1] + b0) * w0
                               + tanh_fast(acc[mt][nt][3] + b1) * w1;
            }
        }
        // Reduce across g (lanes with same tq): xor 4, 8, 16
#pragma unroll
        for (int d = 4; d <= 16; d <<= 1) {
#pragma unroll
            for (int k = 0; k < 4; ++k)
                s[k] += __shfl_xor_sync(0xFFFFFFFFu, s[k], d);
        }
        // Writers: lanes 0..3 cover positions {tq*2, tq*2+1, 8+tq*2, 8+tq*2+1}
        if (lane < 4) {
            sPp[h * 16 + tq * 2]     = s[0];
            sPp[h * 16 + tq * 2 + 1] = s[1];
            sPp[h * 16 + 8 + tq * 2]     = s[2];
            sPp[h * 16 + 8 + tq * 2 + 1] = s[3];
        }
        pair_bar(1 + pr);

        // Epilogue: warp h handles windows ww = h*2 + (lane>>4); 16 lanes per
        // window, each owns a float4 channel chunk.
        const int ww = h * 2 + (lane >> 4);
        const int ck = (lane & 15) * 4;
        const int p  = pw + ww;

        float e0, e1, e2, e3;
        {
            // pos = i*4 + ww; logit = half0 + half1 + br
            float l0 = sPp[ww]      + sPp[16 + ww]      + brv;
            float l1 = sPp[4 + ww]  + sPp[16 + 4 + ww]  + brv;
            float l2 = sPp[8 + ww]  + sPp[16 + 8 + ww]  + brv;
            float l3 = sPp[12 + ww] + sPp[16 + 12 + ww] + brv;
            e0 = __expf(1.0f / (1.0f + __expf(-l0)));
            e1 = __expf(1.0f / (1.0f + __expf(-l1)));
            e2 = __expf(1.0f / (1.0f + __expf(-l2)));
            e3 = __expf(1.0f / (1.0f + __expf(-l3)));
        }
        const float inv = 1.0f / (e0 + e1 + e2 + e3);
        const float g0 = e0 * inv, g1 = e1 * inv, g2 = e2 * inv, g3 = e3 * inv;

        const float* __restrict__ wb = x + ((size_t)row0 * 128 + 2 * p) * 64;
        float4 a4 = *reinterpret_cast<const float4*>(wb + ck);
        float4 b4 = *reinterpret_cast<const float4*>(wb + 64 + ck);
        float4 c4 = *reinterpret_cast<const float4*>(wb + 8192 + ck);
        float4 d4 = *reinterpret_cast<const float4*>(wb + 8192 + 64 + ck);
        float4 o;
        o.x = g0 * a4.x + g1 * b4.x + g2 * c4.x + g3 * d4.x;
        o.y = g0 * a4.y + g1 * b4.y + g2 * c4.y + g3 * d4.y;
        o.z = g0 * a4.z + g1 * b4.z + g2 * c4.z + g3 * d4.z;
        o.w = g0 * a4.w + g1 * b4.w + g2 * c4.w + g3 * d4.w;
        *reinterpret_cast<float4*>(
            out + ((size_t)(b * 64 + q) * 64 + p) * 64 + ck) = o;
    }
}

extern "C" void kernel_launch(void* const* d_in, const int* in_sizes, int n_in,
                              void* d_out, int out_size)
{
    const float* x  = (const float*)d_in[0];
    const float* We = (const float*)d_in[1];
    const float* be = (const float*)d_in[2];
    const float* Wr = (const float*)d_in[3];
    const float* br = (const float*)d_in[4];
    float* out = (float*)d_out;

    cudaFuncSetAttribute(softpool2d_mma_kernel,
                         cudaFuncAttributeMaxDynamicSharedMemorySize, SMEM_SZ);
    // 131072 windows / 64 per CTA = 2048 CTAs
    softpool2d_mma_kernel<<<2048, THREADS, SMEM_SZ>>>(x, We, be, Wr, br, out);
}

// round 13
// speedup vs baseline: 1.3542x; 1.3542x over previous
#include <cuda_runtime.h>
#include <cuda_bf16.h>
#include <cstdint>

// SoftPool_2d: x (32,128,128,64) f32, 2x2/stride-2 windows.
// Round 11: round-9 warp-independent structure, but A (window) fragments for
// 4 tiles (64 positions) are extracted ONCE into resident registers (64 regs),
// and B (We^T) is swept in 16-col chunks -> smem GEMM traffic 384 B/pos vs
// round 9's 768. No cross-warp barriers in the main body (round 10's mistake).

#define THREADS 256

// dynamic smem (bytes)
#define OFF_B    0          // We^T bf16 SW128: 128 rows x 128B  (16384)
#define OFF_A    16384      // per-warp staging: 8 x 2048        (16384)
#define OFF_BIAS 32768      // 128 f32
#define OFF_WR   33280      // 128 f32
#define SMEM_SZ  33792

__device__ __forceinline__ float tanh_fast(float x) {
    float y; asm("tanh.approx.f32 %0, %1;" : "=f"(y) : "f"(x)); return y;
}
__device__ __forceinline__ uint32_t pkbf2(float lo, float hi) {
    __nv_bfloat162 h = __floats2bfloat162_rn(lo, hi);
    return *reinterpret_cast<uint32_t*>(&h);
}
__device__ __forceinline__ void mma16816(float* c, const uint32_t* a,
                                         uint32_t b0, uint32_t b1) {
    asm volatile(
        "mma.sync.aligned.m16n8k16.row.col.f32.bf16.bf16.f32 "
        "{%0,%1,%2,%3}, {%4,%5,%6,%7}, {%8,%9}, {%0,%1,%2,%3};"
        : "+f"(c[0]), "+f"(c[1]), "+f"(c[2]), "+f"(c[3])
        : "r"(a[0]), "r"(a[1]), "r"(a[2]), "r"(a[3]), "r"(b0), "r"(b1));
}
__device__ __forceinline__ void ldsm_x4(uint32_t* r, uint32_t addr) {
    asm volatile("ldmatrix.sync.aligned.m8n8.x4.shared.b16 {%0,%1,%2,%3}, [%4];"
                 : "=r"(r[0]), "=r"(r[1]), "=r"(r[2]), "=r"(r[3]) : "r"(addr));
}
__device__ __forceinline__ uint32_t swz(uint32_t off) {
    return off ^ ((off >> 3) & 0x70);
}

__global__ __launch_bounds__(THREADS, 2)
void softpool2d_mma_kernel(const float* __restrict__ x,
                           const float* __restrict__ We,
                           const float* __restrict__ be,
                           const float* __restrict__ Wr,
                           const float* __restrict__ br,
                           float* __restrict__ out)
{
    extern __shared__ __align__(16) unsigned char smemb[];
    float* sBias = reinterpret_cast<float*>(smemb + OFF_BIAS);
    float* sWr   = reinterpret_cast<float*>(smemb + OFF_WR);

    const int tid  = threadIdx.x;
    const int wid  = tid >> 5;
    const int lane = tid & 31;
    const int g    = lane >> 2;
    const int tq   = lane & 3;

    // Stage We^T (SW128): row j holds We[:,j] as bf16
    {
        uint8_t* bp = smemb + OFF_B;
        for (int idx = tid; idx < 64 * 128; idx += THREADS) {
            int d = idx >> 7;
            int j = idx & 127;
            *reinterpret_cast<__nv_bfloat16*>(bp + swz((uint32_t)(j * 128 + d * 2)))
                = __float2bfloat16(We[idx]);
        }
    }
    if (tid < 128) {
        sBias[tid] = be[tid];
        sWr[tid]   = Wr[tid];
    }
    __syncthreads();          // only CTA-wide barrier

    const float brv = br[0];
    const uint32_t bW = (uint32_t)__cvta_generic_to_shared(smemb + OFF_B);
    const uint32_t aW = (uint32_t)__cvta_generic_to_shared(smemb + OFF_A)
                        + wid * 2048;

    // CTA covers 2 q-rows: b = cta>>5, q0 = (cta&31)*2.
    // Warp: q = q0 + (wid>>2), 16 windows at pw = (wid&3)*16.
    const int cta = blockIdx.x;
    const int b   = cta >> 5;
    const int q   = (cta & 31) * 2 + (wid >> 2);
    const int pw  = (wid & 3) * 16;
    const int row0 = b * 128 + 2 * q;

    const float* __restrict__ baseq = x + ((size_t)row0 * 128 + 2 * pw) * 64;

    const uint32_t arow = (uint32_t)((lane & 15) * 128 + (lane >> 4) * 16);
    const int quad = lane >> 3;
    const uint32_t brow = (uint32_t)(((quad >> 1) * 8 + (lane & 7)) * 128
                                     + (quad & 1) * 16);

    // Extract resident A fragments: 4 tiles x 4 kk, one 2KB buffer reused.
    uint32_t af[4][4][4];
#pragma unroll
    for (int t = 0; t < 4; ++t) {
        const float* __restrict__ bt = baseq + t * 512;
#pragma unroll
        for (int it = 0; it < 8; ++it) {
            int ci = it * 32 + lane;          // 0..255
            int m  = ci >> 4;
            int c4 = ci & 15;
            int i  = m >> 2, w = m & 3;
            const float4 v = *reinterpret_cast<const float4*>(
                bt + (i >> 1) * 8192 + w * 128 + (i & 1) * 64 + c4 * 4);
            uint32_t lo = pkbf2(v.x, v.y);
            uint32_t hi = pkbf2(v.z, v.w);
            asm volatile("st.shared.v2.b32 [%0], {%1,%2};"
                         :: "r"(aW + swz((uint32_t)(m * 128 + c4 * 8))),
                            "r"(lo), "r"(hi) : "memory");
        }
        __syncwarp();
#pragma unroll
        for (int kk = 0; kk < 4; ++kk)
            ldsm_x4(af[t][kk], aW + swz(arow + kk * 32));
        __syncwarp();          // buffer reused by next tile
    }

    float lsA[4] = {0, 0, 0, 0}, lsB[4] = {0, 0, 0, 0};

    // Sweep hidden in 8 chunks of 16 cols; B fragment read once per (chunk,kk).
#pragma unroll
    for (int h = 0; h < 8; ++h) {
        float acc[4][2][4];
#pragma unroll
        for (int t = 0; t < 4; ++t)
#pragma unroll
            for (int n = 0; n < 2; ++n)
#pragma unroll
                for (int c = 0; c < 4; ++c) acc[t][n][c] = 0.0f;

#pragma unroll
        for (int kk = 0; kk < 4; ++kk) {
            uint32_t brr[4];
            ldsm_x4(brr, bW + swz((uint32_t)(h * 2048) + brow + kk * 32));
#pragma unroll
            for (int t = 0; t < 4; ++t) {
                mma16816(acc[t][0], af[t][kk], brr[0], brr[1]);
                mma16816(acc[t][1], af[t][kk], brr[2], brr[3]);
            }
        }

        // Fold this chunk into logit partial dots.
        // Lane rows: g (lsA), g+8 (lsB); cols j = h*16 + n*8 + tq*2 {+1}.
#pragma unroll
        for (int n = 0; n < 2; ++n) {
            const int j = h * 16 + n * 8 + tq * 2;
            float2 bia = *reinterpret_cast<const float2*>(&sBias[j]);
            float2 wr2 = *reinterpret_cast<const float2*>(&sWr[j]);
#pragma unroll
            for (int t = 0; t < 4; ++t) {
                lsA[t] = fmaf(tanh_fast(acc[t][n][0] + bia.x), wr2.x, lsA[t]);
                lsA[t] = fmaf(tanh_fast(acc[t][n][1] + bia.y), wr2.y, lsA[t]);
                lsB[t] = fmaf(tanh_fast(acc[t][n][2] + bia.x), wr2.x, lsB[t]);
                lsB[t] = fmaf(tanh_fast(acc[t][n][3] + bia.y), wr2.y, lsB[t]);
            }
        }
    }

    // Per-tile softmax + weighted sum (identical to round 9, warp-local).
#pragma unroll
    for (int t = 0; t < 4; ++t) {
        float a = lsA[t], bb = lsB[t];
        a += __shfl_xor_sync(0xFFFFFFFFu, a, 1);
        a += __shfl_xor_sync(0xFFFFFFFFu, a, 2);
        bb += __shfl_xor_sync(0xFFFFFFFFu, bb, 1);
        bb += __shfl_xor_sync(0xFFFFFFFFu, bb, 2);

        // logit in (0,1); unnormalized softmax weight e = exp(logit) in (1,e)
        const float eA = __expf(1.0f / (1.0f + __expf(-(a + brv))));
        const float eB = __expf(1.0f / (1.0f + __expf(-(bb + brv))));
        const float pA = __shfl_xor_sync(0xFFFFFFFFu, eA, 16);
        const float pB = __shfl_xor_sync(0xFFFFFFFFu, eB, 16);

        float e0, e1, e2, e3;
        if (g < 4) { e0 = eA; e2 = eB; e1 = pA; e3 = pB; }
        else       { e1 = eA; e3 = eB; e0 = pA; e2 = pB; }
        const float inv = 1.0f / (e0 + e1 + e2 + e3);
        const float g0 = e0 * inv, g1 = e1 * inv, g2 = e2 * inv, g3 = e3 * inv;

        // Window w served by its 8 lanes; lane owns 2 contiguous 16B chunks.
        const int w   = g & 3;
        const int sub = ((g >> 2) << 2) + tq;     // 0..7
        const int p   = pw + t * 4 + w;
        const float* __restrict__ wb = x + ((size_t)row0 * 128 + 2 * p) * 64;
        float* __restrict__ dst = out + ((size_t)(b * 64 + q) * 64 + p) * 64;

#pragma unroll
        for (int hh = 0; hh < 2; ++hh) {
            const int off = hh * 32 + sub * 4;
            float4 a4 = *reinterpret_cast<const float4*>(wb + off);
            float4 b4 = *reinterpret_cast<const float4*>(wb + 64 + off);
            float4 c4 = *reinterpret_cast<const float4*>(wb + 8192 + off);
            float4 d4 = *reinterpret_cast<const float4*>(wb + 8192 + 64 + off);
            float4 o;
            o.x = g0 * a4.x + g1 * b4.x + g2 * c4.x + g3 * d4.x;
            o.y = g0 * a4.y + g1 * b4.y + g2 * c4.y + g3 * d4.y;
            o.z = g0 * a4.z + g1 * b4.z + g2 * c4.z + g3 * d4.z;
            o.w = g0 * a4.w + g1 * b4.w + g2 * c4.w + g3 * d4.w;
            *reinterpret_cast<float4*>(dst + off) = o;
        }
    }
}

extern "C" void kernel_launch(void* const* d_in, const int* in_sizes, int n_in,
                              void* d_out, int out_size)
{
    const float* x  = (const float*)d_in[0];
    const float* We = (const float*)d_in[1];
    const float* be = (const float*)d_in[2];
    const float* Wr = (const float*)d_in[3];
    const float* br = (const float*)d_in[4];
    float* out = (float*)d_out;

    cudaFuncSetAttribute(softpool2d_mma_kernel,
                         cudaFuncAttributeMaxDynamicSharedMemorySize, SMEM_SZ);
    // 131072 windows / 128 per CTA = 1024 CTAs
    softpool2d_mma_kernel<<<1024, THREADS, SMEM_SZ>>>(x, We, be, Wr, br, out);
}

// round 15
// speedup vs baseline: 1.3975x; 1.0320x over previous
#include <cuda_runtime.h>
#include <cuda_bf16.h>
#include <cstdint>

// SoftPool_2d: x (32,128,128,64) f32, 2x2/stride-2 windows.
// Round 14: identical traffic/numerics to round 11 (57.8us), latency-hiding
// only: (1) software-pipelined A staging with double-buffered per-warp smem,
// (2) 2-deep rotating prefetch of B ldsm fragments, (3) epilogue x loads
// hoisted above the gate (shfl/exp) dependency chain.

#define THREADS 256

// dynamic smem (bytes)
#define OFF_B    0          // We^T bf16 SW128: 128 rows x 128B  (16384)
#define OFF_A    16384      // per-warp staging: 8 warps x 2 bufs x 2048 (32768)
#define OFF_BIAS 49152      // 128 f32
#define OFF_WR   49664      // 128 f32
#define SMEM_SZ  50176

__device__ __forceinline__ float tanh_fast(float x) {
    float y; asm("tanh.approx.f32 %0, %1;" : "=f"(y) : "f"(x)); return y;
}
__device__ __forceinline__ uint32_t pkbf2(float lo, float hi) {
    __nv_bfloat162 h = __floats2bfloat162_rn(lo, hi);
    return *reinterpret_cast<uint32_t*>(&h);
}
__device__ __forceinline__ void mma16816(float* c, const uint32_t* a,
                                         uint32_t b0, uint32_t b1) {
    asm volatile(
        "mma.sync.aligned.m16n8k16.row.col.f32.bf16.bf16.f32 "
        "{%0,%1,%2,%3}, {%4,%5,%6,%7}, {%8,%9}, {%0,%1,%2,%3};"
        : "+f"(c[0]), "+f"(c[1]), "+f"(c[2]), "+f"(c[3])
        : "r"(a[0]), "r"(a[1]), "r"(a[2]), "r"(a[3]), "r"(b0), "r"(b1));
}
__device__ __forceinline__ void ldsm_x4(uint32_t* r, uint32_t addr) {
    asm volatile("ldmatrix.sync.aligned.m8n8.x4.shared.b16 {%0,%1,%2,%3}, [%4];"
                 : "=r"(r[0]), "=r"(r[1]), "=r"(r[2]), "=r"(r[3]) : "r"(addr));
}
__device__ __forceinline__ uint32_t swz(uint32_t off) {
    return off ^ ((off >> 3) & 0x70);
}

__global__ __launch_bounds__(THREADS, 2)
void softpool2d_mma_kernel(const float* __restrict__ x,
                           const float* __restrict__ We,
                           const float* __restrict__ be,
                           const float* __restrict__ Wr,
                           const float* __restrict__ br,
                           float* __restrict__ out)
{
    extern __shared__ __align__(16) unsigned char smemb[];
    float* sBias = reinterpret_cast<float*>(smemb + OFF_BIAS);
    float* sWr   = reinterpret_cast<float*>(smemb + OFF_WR);

    const int tid  = threadIdx.x;
    const int wid  = tid >> 5;
    const int lane = tid & 31;
    const int g    = lane >> 2;
    const int tq   = lane & 3;

    // Stage We^T (SW128): row j holds We[:,j] as bf16
    {
        uint8_t* bp = smemb + OFF_B;
        for (int idx = tid; idx < 64 * 128; idx += THREADS) {
            int d = idx >> 7;
            int j = idx & 127;
            *reinterpret_cast<__nv_bfloat16*>(bp + swz((uint32_t)(j * 128 + d * 2)))
                = __float2bfloat16(We[idx]);
        }
    }
    if (tid < 128) {
        sBias[tid] = be[tid];
        sWr[tid]   = Wr[tid];
    }
    __syncthreads();          // only CTA-wide barrier

    const float brv = br[0];
    const uint32_t bW = (uint32_t)__cvta_generic_to_shared(smemb + OFF_B);
    const uint32_t aW = (uint32_t)__cvta_generic_to_shared(smemb + OFF_A)
                        + wid * 4096;     // 2 x 2KB buffers per warp

    // CTA covers 2 q-rows: b = cta>>5, q0 = (cta&31)*2.
    // Warp: q = q0 + (wid>>2), 16 windows at pw = (wid&3)*16.
    const int cta = blockIdx.x;
    const int b   = cta >> 5;
    const int q   = (cta & 31) * 2 + (wid >> 2);
    const int pw  = (wid & 3) * 16;
    const int row0 = b * 128 + 2 * q;

    const float* __restrict__ baseq = x + ((size_t)row0 * 128 + 2 * pw) * 64;

    const uint32_t arow = (uint32_t)((lane & 15) * 128 + (lane >> 4) * 16);
    const int quad = lane >> 3;
    const uint32_t brow = (uint32_t)(((quad >> 1) * 8 + (lane & 7)) * 128
                                     + (quad & 1) * 16);

    // Per-tile LDG: thread's 8 chunk indices are fixed; src depends on tile.
    // ci = it*32 + lane; m = ci>>4; c4 = ci&15; i = m>>2; w = m&3.
    // offset(t) = t*512 + (i>>1)*8192 + w*128 + (i&1)*64 + c4*4.
    int srcoff[8];
    uint32_t stoff[8];
#pragma unroll
    for (int it = 0; it < 8; ++it) {
        int ci = it * 32 + lane;
        int m  = ci >> 4;
        int c4 = ci & 15;
        int i  = m >> 2, w = m & 3;
        srcoff[it] = (i >> 1) * 8192 + w * 128 + (i & 1) * 64 + c4 * 4;
        stoff[it]  = swz((uint32_t)(m * 128 + c4 * 8));
    }

    // --- Software-pipelined A staging: LDG(t+1) overlaps STS/ldsm(t) ---
    uint32_t af[4][4][4];
    float4 v[8], vn[8];
#pragma unroll
    for (int it = 0; it < 8; ++it)
        v[it] = *reinterpret_cast<const float4*>(baseq + srcoff[it]);

#pragma unroll
    for (int t = 0; t < 4; ++t) {
        if (t < 3) {
            const float* __restrict__ bn = baseq + (t + 1) * 512;
#pragma unroll
            for (int it = 0; it < 8; ++it)
                vn[it] = *reinterpret_cast<const float4*>(bn + srcoff[it]);
        }
        const uint32_t buf = aW + (uint32_t)((t & 1) * 2048);
#pragma unroll
        for (int it = 0; it < 8; ++it) {
            uint32_t lo = pkbf2(v[it].x, v[it].y);
            uint32_t hi = pkbf2(v[it].z, v[it].w);
            asm volatile("st.shared.v2.b32 [%0], {%1,%2};"
                         :: "r"(buf + stoff[it]), "r"(lo), "r"(hi) : "memory");
        }
        __syncwarp();
#pragma unroll
        for (int kk = 0; kk < 4; ++kk)
            ldsm_x4(af[t][kk], buf + swz(arow + kk * 32));
        // ldmatrix is warp-collective: all lanes pass it before any lane's
        // next STS to this buffer (2 tiles later). No extra syncwarp needed.
#pragma unroll
        for (int it = 0; it < 8; ++it) v[it] = vn[it];
    }

    float lsA[4] = {0, 0, 0, 0}, lsB[4] = {0, 0, 0, 0};

    // --- Hidden sweep, 8 chunks of 16 cols; B fragments 2-deep prefetched ---
    uint32_t brr[2][4];
    ldsm_x4(brr[0], bW + swz(brow));     // (h=0, kk=0)
    int pb = 0;

#pragma unroll
    for (int h = 0; h < 8; ++h) {
        float acc[4][2][4];
#pragma unroll
        for (int t = 0; t < 4; ++t)
#pragma unroll
            for (int n = 0; n < 2; ++n)
#pragma unroll
                for (int c = 0; c < 4; ++c) acc[t][n][c] = 0.0f;

#pragma unroll
        for (int kk = 0; kk < 4; ++kk) {
            if (!(h == 7 && kk == 3)) {
                const int nh  = (kk == 3) ? h + 1 : h;
                const int nkk = (kk + 1) & 3;
                ldsm_x4(brr[pb ^ 1],
                        bW + swz((uint32_t)(nh * 2048) + brow + nkk * 32));
            }
#pragma unroll
            for (int t = 0; t < 4; ++t) {
                mma16816(acc[t][0], af[t][kk], brr[pb][0], brr[pb][1]);
                mma16816(acc[t][1], af[t][kk], brr[pb][2], brr[pb][3]);
            }
            pb ^= 1;
        }

        // Fold chunk into logit partials. Lane rows: g (lsA), g+8 (lsB).
#pragma unroll
        for (int n = 0; n < 2; ++n) {
            const int j = h * 16 + n * 8 + tq * 2;
            float2 bia = *reinterpret_cast<const float2*>(&sBias[j]);
            float2 wr2 = *reinterpret_cast<const float2*>(&sWr[j]);
#pragma unroll
            for (int t = 0; t < 4; ++t) {
                lsA[t] = fmaf(tanh_fast(acc[t][n][0] + bia.x), wr2.x, lsA[t]);
                lsA[t] = fmaf(tanh_fast(acc[t][n][1] + bia.y), wr2.y, lsA[t]);
                lsB[t] = fmaf(tanh_fast(acc[t][n][2] + bia.x), wr2.x, lsB[t]);
                lsB[t] = fmaf(tanh_fast(acc[t][n][3] + bia.y), wr2.y, lsB[t]);
            }
        }
    }

    // --- Per-tile softmax + weighted sum; x loads hoisted above gate chain ---
    const int w   = g & 3;
    const int sub = ((g >> 2) << 2) + tq;     // 0..7
#pragma unroll
    for (int t = 0; t < 4; ++t) {
        const int p = pw + t * 4 + w;
        const float* __restrict__ wb = x + ((size_t)row0 * 128 + 2 * p) * 64;

        // Issue all 8 loads first (independent of the gate computation).
        float4 xa[2], xb[2], xc[2], xd[2];
#pragma unroll
        for (int hh = 0; hh < 2; ++hh) {
            const int off = hh * 32 + sub * 4;
            xa[hh] = *reinterpret_cast<const float4*>(wb + off);
            xb[hh] = *reinterpret_cast<const float4*>(wb + 64 + off);
            xc[hh] = *reinterpret_cast<const float4*>(wb + 8192 + off);
            xd[hh] = *reinterpret_cast<const float4*>(wb + 8192 + 64 + off);
        }

        float a = lsA[t], bb = lsB[t];
        a += __shfl_xor_sync(0xFFFFFFFFu, a, 1);
        a += __shfl_xor_sync(0xFFFFFFFFu, a, 2);
        bb += __shfl_xor_sync(0xFFFFFFFFu, bb, 1);
        bb += __shfl_xor_sync(0xFFFFFFFFu, bb, 2);

        // logit in (0,1); unnormalized softmax weight e = exp(logit) in (1,e)
        const float eA = __expf(1.0f / (1.0f + __expf(-(a + brv))));
        const float eB = __expf(1.0f / (1.0f + __expf(-(bb + brv))));
        const float pA = __shfl_xor_sync(0xFFFFFFFFu, eA, 16);
        const float pB = __shfl_xor_sync(0xFFFFFFFFu, eB, 16);

        float e0, e1, e2, e3;
        if (g < 4) { e0 = eA; e2 = eB; e1 = pA; e3 = pB; }
        else       { e1 = eA; e3 = eB; e0 = pA; e2 = pB; }
        const float inv = 1.0f / (e0 + e1 + e2 + e3);
        const float g0 = e0 * inv, g1 = e1 * inv, g2 = e2 * inv, g3 = e3 * inv;

        float* __restrict__ dst = out + ((size_t)(b * 64 + q) * 64 + p) * 64;
#pragma unroll
        for (int hh = 0; hh < 2; ++hh) {
            const int off = hh * 32 + sub * 4;
            float4 o;
            o.x = g0 * xa[hh].x + g1 * xb[hh].x + g2 * xc[hh].x + g3 * xd[hh].x;
            o.y = g0 * xa[hh].y + g1 * xb[hh].y + g2 * xc[hh].y + g3 * xd[hh].y;
            o.z = g0 * xa[hh].z + g1 * xb[hh].z + g2 * xc[hh].z + g3 * xd[hh].z;
            o.w = g0 * xa[hh].w + g1 * xb[hh].w + g2 * xc[hh].w + g3 * xd[hh].w;
            *reinterpret_cast<float4*>(dst + off) = o;
        }
    }
}

extern "C" void kernel_launch(void* const* d_in, const int* in_sizes, int n_in,
                              void* d_out, int out_size)
{
    const float* x  = (const float*)d_in[0];
    const float* We = (const float*)d_in[1];
    const float* be = (const float*)d_in[2];
    const float* Wr = (const float*)d_in[3];
    const float* br = (const float*)d_in[4];
    float* out = (float*)d_out;

    cudaFuncSetAttribute(softpool2d_mma_kernel,
                         cudaFuncAttributeMaxDynamicSharedMemorySize, SMEM_SZ);
    // 131072 windows / 128 per CTA = 1024 CTAs
    softpool2d_mma_kernel<<<1024, THREADS, SMEM_SZ>>>(x, We, be, Wr, br, out);
}

// round 16
// speedup vs baseline: 1.4039x; 1.0046x over previous
#include <cuda_runtime.h>
#include <cuda_bf16.h>
#include <cstdint>

// SoftPool_2d: x (32,128,128,64) f32, 2x2/stride-2 windows.
// Round 16: round-14 traffic/numerics, but the A-prologue is split into two
// register-disjoint phases: (1) pipelined staging of all 4 tiles into a
// per-warp 8KB smem region (only v/vn live), (2) bulk ldsm extraction of all
// 16 af fragments (only af live). Removes the 125+ reg peak that round 14's
// interleaved prologue created, plus 7 syncwarps.

#define THREADS 256

// dynamic smem (bytes)
#define OFF_B    0          // We^T bf16 SW128: 128 rows x 128B  (16384)
#define OFF_A    16384      // per-warp staging: 8 warps x 4 tiles x 2048 (65536)
#define OFF_BIAS 81920      // 128 f32
#define OFF_WR   82432      // 128 f32
#define SMEM_SZ  82944

__device__ __forceinline__ float tanh_fast(float x) {
    float y; asm("tanh.approx.f32 %0, %1;" : "=f"(y) : "f"(x)); return y;
}
__device__ __forceinline__ uint32_t pkbf2(float lo, float hi) {
    __nv_bfloat162 h = __floats2bfloat162_rn(lo, hi);
    return *reinterpret_cast<uint32_t*>(&h);
}
__device__ __forceinline__ void mma16816(float* c, const uint32_t* a,
                                         uint32_t b0, uint32_t b1) {
    asm volatile(
        "mma.sync.aligned.m16n8k16.row.col.f32.bf16.bf16.f32 "
        "{%0,%1,%2,%3}, {%4,%5,%6,%7}, {%8,%9}, {%0,%1,%2,%3};"
        : "+f"(c[0]), "+f"(c[1]), "+f"(c[2]), "+f"(c[3])
        : "r"(a[0]), "r"(a[1]), "r"(a[2]), "r"(a[3]), "r"(b0), "r"(b1));
}
__device__ __forceinline__ void ldsm_x4(uint32_t* r, uint32_t addr) {
    asm volatile("ldmatrix.sync.aligned.m8n8.x4.shared.b16 {%0,%1,%2,%3}, [%4];"
                 : "=r"(r[0]), "=r"(r[1]), "=r"(r[2]), "=r"(r[3]) : "r"(addr));
}
__device__ __forceinline__ uint32_t swz(uint32_t off) {
    return off ^ ((off >> 3) & 0x70);
}

__global__ __launch_bounds__(THREADS, 2)
void softpool2d_mma_kernel(const float* __restrict__ x,
                           const float* __restrict__ We,
                           const float* __restrict__ be,
                           const float* __restrict__ Wr,
                           const float* __restrict__ br,
                           float* __restrict__ out)
{
    extern __shared__ __align__(16) unsigned char smemb[];
    float* sBias = reinterpret_cast<float*>(smemb + OFF_BIAS);
    float* sWr   = reinterpret_cast<float*>(smemb + OFF_WR);

    const int tid  = threadIdx.x;
    const int wid  = tid >> 5;
    const int lane = tid & 31;
    const int g    = lane >> 2;
    const int tq   = lane & 3;

    // Stage We^T (SW128): row j holds We[:,j] as bf16
    {
        uint8_t* bp = smemb + OFF_B;
        for (int idx = tid; idx < 64 * 128; idx += THREADS) {
            int d = idx >> 7;
            int j = idx & 127;
            *reinterpret_cast<__nv_bfloat16*>(bp + swz((uint32_t)(j * 128 + d * 2)))
                = __float2bfloat16(We[idx]);
        }
    }
    if (tid < 128) {
        sBias[tid] = be[tid];
        sWr[tid]   = Wr[tid];
    }
    __syncthreads();          // only CTA-wide barrier

    const float brv = br[0];
    const uint32_t bW = (uint32_t)__cvta_generic_to_shared(smemb + OFF_B);
    const uint32_t aW = (uint32_t)__cvta_generic_to_shared(smemb + OFF_A)
                        + wid * 8192;     // 4 x 2KB tile buffers per warp

    // CTA covers 2 q-rows: b = cta>>5, q0 = (cta&31)*2.
    // Warp: q = q0 + (wid>>2), 16 windows at pw = (wid&3)*16.
    const int cta = blockIdx.x;
    const int b   = cta >> 5;
    const int q   = (cta & 31) * 2 + (wid >> 2);
    const int pw  = (wid & 3) * 16;
    const int row0 = b * 128 + 2 * q;

    const float* __restrict__ baseq = x + ((size_t)row0 * 128 + 2 * pw) * 64;

    const uint32_t arow = (uint32_t)((lane & 15) * 128 + (lane >> 4) * 16);
    const int quad = lane >> 3;
    const uint32_t brow = (uint32_t)(((quad >> 1) * 8 + (lane & 7)) * 128
                                     + (quad & 1) * 16);

    // Per-tile chunk addressing (fixed per thread):
    // ci = it*32 + lane; m = ci>>4; c4 = ci&15; i = m>>2; w = m&3.
    int srcoff[8];
    uint32_t stoff[8];
#pragma unroll
    for (int it = 0; it < 8; ++it) {
        int ci = it * 32 + lane;
        int m  = ci >> 4;
        int c4 = ci & 15;
        int i  = m >> 2, w = m & 3;
        srcoff[it] = (i >> 1) * 8192 + w * 128 + (i & 1) * 64 + c4 * 4;
        stoff[it]  = swz((uint32_t)(m * 128 + c4 * 8));
    }

    // --- Phase 1: stage all 4 tiles (pipelined LDG; no af live) ---
    {
        float4 v[8], vn[8];
#pragma unroll
        for (int it = 0; it < 8; ++it)
            v[it] = *reinterpret_cast<const float4*>(baseq + srcoff[it]);
#pragma unroll
        for (int t = 0; t < 4; ++t) {
            if (t < 3) {
                const float* __restrict__ bn = baseq + (t + 1) * 512;
#pragma unroll
                for (int it = 0; it < 8; ++it)
                    vn[it] = *reinterpret_cast<const float4*>(bn + srcoff[it]);
            }
            const uint32_t buf = aW + (uint32_t)(t * 2048);
#pragma unroll
            for (int it = 0; it < 8; ++it) {
                uint32_t lo = pkbf2(v[it].x, v[it].y);
                uint32_t hi = pkbf2(v[it].z, v[it].w);
                asm volatile("st.shared.v2.b32 [%0], {%1,%2};"
                             :: "r"(buf + stoff[it]), "r"(lo), "r"(hi) : "memory");
            }
#pragma unroll
            for (int it = 0; it < 8; ++it) v[it] = vn[it];
        }
    }
    __syncwarp();

    // --- Phase 2: extract all 16 af fragments (no v/vn live) ---
    uint32_t af[4][4][4];
#pragma unroll
    for (int t = 0; t < 4; ++t)
#pragma unroll
        for (int kk = 0; kk < 4; ++kk)
            ldsm_x4(af[t][kk], aW + (uint32_t)(t * 2048) + swz(arow + kk * 32));

    float lsA[4] = {0, 0, 0, 0}, lsB[4] = {0, 0, 0, 0};

    // --- Hidden sweep, 8 chunks of 16 cols; B fragments 2-deep prefetched ---
    uint32_t brr[2][4];
    ldsm_x4(brr[0], bW + swz(brow));     // (h=0, kk=0)
    int pb = 0;

#pragma unroll
    for (int h = 0; h < 8; ++h) {
        float acc[4][2][4];
#pragma unroll
        for (int t = 0; t < 4; ++t)
#pragma unroll
            for (int n = 0; n < 2; ++n)
#pragma unroll
                for (int c = 0; c < 4; ++c) acc[t][n][c] = 0.0f;

#pragma unroll
        for (int kk = 0; kk < 4; ++kk) {
            if (!(h == 7 && kk == 3)) {
                const int nh  = (kk == 3) ? h + 1 : h;
                const int nkk = (kk + 1) & 3;
                ldsm_x4(brr[pb ^ 1],
                        bW + swz((uint32_t)(nh * 2048) + brow + nkk * 32));
            }
#pragma unroll
            for (int t = 0; t < 4; ++t) {
                mma16816(acc[t][0], af[t][kk], brr[pb][0], brr[pb][1]);
                mma16816(acc[t][1], af[t][kk], brr[pb][2], brr[pb][3]);
            }
            pb ^= 1;
        }

        // Fold chunk into logit partials. Lane rows: g (lsA), g+8 (lsB).
#pragma unroll
        for (int n = 0; n < 2; ++n) {
            const int j = h * 16 + n * 8 + tq * 2;
            float2 bia = *reinterpret_cast<const float2*>(&sBias[j]);
            float2 wr2 = *reinterpret_cast<const float2*>(&sWr[j]);
#pragma unroll
            for (int t = 0; t < 4; ++t) {
                lsA[t] = fmaf(tanh_fast(acc[t][n][0] + bia.x), wr2.x, lsA[t]);
                lsA[t] = fmaf(tanh_fast(acc[t][n][1] + bia.y), wr2.y, lsA[t]);
                lsB[t] = fmaf(tanh_fast(acc[t][n][2] + bia.x), wr2.x, lsB[t]);
                lsB[t] = fmaf(tanh_fast(acc[t][n][3] + bia.y), wr2.y, lsB[t]);
            }
        }
    }

    // --- Per-tile softmax + weighted sum; x loads hoisted above gate chain ---
    const int w   = g & 3;
    const int sub = ((g >> 2) << 2) + tq;     // 0..7
#pragma unroll
    for (int t = 0; t < 4; ++t) {
        const int p = pw + t * 4 + w;
        const float* __restrict__ wb = x + ((size_t)row0 * 128 + 2 * p) * 64;

        // Issue all 8 loads first (independent of the gate computation).
        float4 xa[2], xb[2], xc[2], xd[2];
#pragma unroll
        for (int hh = 0; hh < 2; ++hh) {
            const int off = hh * 32 + sub * 4;
            xa[hh] = *reinterpret_cast<const float4*>(wb + off);
            xb[hh] = *reinterpret_cast<const float4*>(wb + 64 + off);
            xc[hh] = *reinterpret_cast<const float4*>(wb + 8192 + off);
            xd[hh] = *reinterpret_cast<const float4*>(wb + 8192 + 64 + off);
        }

        float a = lsA[t], bb = lsB[t];
        a += __shfl_xor_sync(0xFFFFFFFFu, a, 1);
        a += __shfl_xor_sync(0xFFFFFFFFu, a, 2);
        bb += __shfl_xor_sync(0xFFFFFFFFu, bb, 1);
        bb += __shfl_xor_sync(0xFFFFFFFFu, bb, 2);

        // logit in (0,1); unnormalized softmax weight e = exp(logit) in (1,e)
        const float eA = __expf(1.0f / (1.0f + __expf(-(a + brv))));
        const float eB = __expf(1.0f / (1.0f + __expf(-(bb + brv))));
        const float pA = __shfl_xor_sync(0xFFFFFFFFu, eA, 16);
        const float pB = __shfl_xor_sync(0xFFFFFFFFu, eB, 16);

        float e0, e1, e2, e3;
        if (g < 4) { e0 = eA; e2 = eB; e1 = pA; e3 = pB; }
        else       { e1 = eA; e3 = eB; e0 = pA; e2 = pB; }
        const float inv = 1.0f / (e0 + e1 + e2 + e3);
        const float g0 = e0 * inv, g1 = e1 * inv, g2 = e2 * inv, g3 = e3 * inv;

        float* __restrict__ dst = out + ((size_t)(b * 64 + q) * 64 + p) * 64;
#pragma unroll
        for (int hh = 0; hh < 2; ++hh) {
            const int off = hh * 32 + sub * 4;
            float4 o;
            o.x = g0 * xa[hh].x + g1 * xb[hh].x + g2 * xc[hh].x + g3 * xd[hh].x;
            o.y = g0 * xa[hh].y + g1 * xb[hh].y + g2 * xc[hh].y + g3 * xd[hh].y;
            o.z = g0 * xa[hh].z + g1 * xb[hh].z + g2 * xc[hh].z + g3 * xd[hh].z;
            o.w = g0 * xa[hh].w + g1 * xb[hh].w + g2 * xc[hh].w + g3 * xd[hh].w;
            *reinterpret_cast<float4*>(dst + off) = o;
        }
    }
}

extern "C" void kernel_launch(void* const* d_in, const int* in_sizes, int n_in,
                              void* d_out, int out_size)
{
    const float* x  = (const float*)d_in[0];
    const float* We = (const float*)d_in[1];
    const float* be = (const float*)d_in[2];
    const float* Wr = (const float*)d_in[3];
    const float* br = (const float*)d_in[4];
    float* out = (float*)d_out;

    cudaFuncSetAttribute(softpool2d_mma_kernel,
                         cudaFuncAttributeMaxDynamicSharedMemorySize, SMEM_SZ);
    // 131072 windows / 128 per CTA = 1024 CTAs
    softpool2d_mma_kernel<<<1024, THREADS, SMEM_SZ>>>(x, We, be, Wr, br, out);
}